// round 12
// baseline (speedup 1.0000x reference)
#include <cuda_runtime.h>
#include <math.h>
#include <stdint.h>

#define B_MAX 4096

typedef unsigned long long u64;

// Scratch: conv1 pooled output in k2-ready padded layout [B][16ch][16][16]
// (row/col 0 and 15 are zero borders), plus dense angles [B][4].
__device__ float g_h1[B_MAX * 4096];
__device__ float g_ang[B_MAX * 4];

// ---------------------------------------------------------------------------
// f32x2 packed-FMA helpers (k1 only)
// ---------------------------------------------------------------------------
__device__ __forceinline__ u64 pack2(float lo, float hi) {
    u64 r; asm("mov.b64 %0, {%1,%2};" : "=l"(r) : "f"(lo), "f"(hi)); return r;
}
__device__ __forceinline__ void unpack2(u64 v, float& lo, float& hi) {
    asm("mov.b64 {%0,%1}, %2;" : "=f"(lo), "=f"(hi) : "l"(v));
}
__device__ __forceinline__ u64 ffma2(u64 a, u64 b, u64 c) {
    u64 d; asm("fma.rn.f32x2 %0, %1, %2, %3;" : "=l"(d) : "l"(a), "l"(b), "l"(c));
    return d;
}

// ---------------------------------------------------------------------------
// tf32 helpers
// ---------------------------------------------------------------------------
__device__ __forceinline__ uint32_t f2tf32(float x) {
    uint32_t r; asm("cvt.rna.tf32.f32 %0, %1;" : "=r"(r) : "f"(x)); return r;
}
__device__ __forceinline__ void mma_tf32(float c[4],
    uint32_t a0, uint32_t a1, uint32_t a2, uint32_t a3,
    uint32_t b0, uint32_t b1)
{
    asm volatile(
        "mma.sync.aligned.m16n8k8.row.col.f32.tf32.tf32.f32 "
        "{%0,%1,%2,%3}, {%4,%5,%6,%7}, {%8,%9}, {%0,%1,%2,%3};"
        : "+f"(c[0]), "+f"(c[1]), "+f"(c[2]), "+f"(c[3])
        : "r"(a0), "r"(a1), "r"(a2), "r"(a3), "r"(b0), "r"(b1));
}

// ---------------------------------------------------------------------------
// Kernel 1: conv1 (1->16) + ReLU + 2x2 pool. [R4 version — measured 34.2us]
// ---------------------------------------------------------------------------
#define K1S 34

__global__ __launch_bounds__(196, 4) void k1_conv1(
    const float* __restrict__ x, const float* __restrict__ w,
    const float* __restrict__ b)
{
    __shared__ float sxp[30 * K1S];   // zero-padded 30x30 input
    __shared__ u64 swp[80];           // [8 cg][9] packed weights + [8] packed bias

    const int img = blockIdx.x;
    const int t = threadIdx.x;
    const float* xi = x + img * 784;

    for (int i = t; i < 30 * K1S; i += 196) sxp[i] = 0.f;
    if (t < 72)      swp[t] = pack2(w[t], w[t + 72]);          // cg=t/9,k=t%9
    else if (t < 80) swp[t] = pack2(b[t - 72], b[t - 64]);
    __syncthreads();
#pragma unroll
    for (int k = 0; k < 4; k++) {                 // 784 = 4*196 exactly
        int i = t + k * 196;
        int r = i / 28, c = i % 28;
        sxp[(r + 1) * K1S + (c + 1)] = xi[i];
    }
    __syncthreads();

    const int pr = t / 14;
    const int pc = t % 14;

    u64 pv[16];
    {
        const float* p0 = &sxp[(2 * pr) * K1S + 2 * pc];
#pragma unroll
        for (int j = 0; j < 4; j++) {
            float2 a  = *(const float2*)(p0 + j * K1S);
            float2 bq = *(const float2*)(p0 + j * K1S + 2);
            pv[j * 4 + 0] = pack2(a.x, a.x);
            pv[j * 4 + 1] = pack2(a.y, a.y);
            pv[j * 4 + 2] = pack2(bq.x, bq.x);
            pv[j * 4 + 3] = pack2(bq.y, bq.y);
        }
    }

    float* outp = g_h1 + (long)img * 4096 + (pr + 1) * 16 + (pc + 1);

#pragma unroll
    for (int cg = 0; cg < 8; cg++) {
        u64 wp[9];
#pragma unroll
        for (int k = 0; k < 9; k++) wp[k] = swp[cg * 9 + k];
        const u64 bb = swp[72 + cg];
        u64 acc[4] = {bb, bb, bb, bb};
#pragma unroll
        for (int kr = 0; kr < 3; kr++)
#pragma unroll
            for (int kc = 0; kc < 3; kc++) {
                const u64 wv = wp[kr * 3 + kc];
#pragma unroll
                for (int dr = 0; dr < 2; dr++)
#pragma unroll
                    for (int dc = 0; dc < 2; dc++)
                        acc[dr * 2 + dc] =
                            ffma2(pv[(dr + kr) * 4 + (dc + kc)], wv, acc[dr * 2 + dc]);
            }
        float l0, h0, l1, h1, l2, h2, l3, h3;
        unpack2(acc[0], l0, h0); unpack2(acc[1], l1, h1);
        unpack2(acc[2], l2, h2); unpack2(acc[3], l3, h3);
        float mlo = fmaxf(fmaxf(fmaxf(l0, l1), fmaxf(l2, l3)), 0.f);
        float mhi = fmaxf(fmaxf(fmaxf(h0, h1), fmaxf(h2, h3)), 0.f);
        outp[cg * 256]       = mlo;
        outp[(cg + 8) * 256] = mhi;
    }

    for (int i = t; i < 960; i += 196) {
        int ch = i / 60, j = i % 60;
        int r, c;
        if (j < 16)      { r = 0;  c = j; }
        else if (j < 32) { r = 15; c = j - 16; }
        else if (j < 46) { r = j - 31; c = 0; }
        else             { r = j - 45; c = 15; }
        g_h1[(long)img * 4096 + ch * 256 + r * 16 + c] = 0.f;
    }
}

// ---------------------------------------------------------------------------
// Kernel 2: conv2 as implicit-GEMM tf32 tensor-core (3xTF32) + pool + dense.
// One image per CTA, 256 threads = 8 warps. Warp w: m-tile = w&1 (16 ocs),
// n-tiles = (w>>1) + 4j (8 positions each, N=196 padded to 200).
// K = 144 = 9 taps x 16 ic, 18 k-steps of 8. B gathered from padded smem
// tile (channel stride 264 -> conflict-free fragment loads).
// ---------------------------------------------------------------------------
#define SM_SIN  0                    // 16*264 = 4224 floats
#define SM_AH   4224                 // 18*288 = 5184 u32 (tf32 hi)
#define SM_AL   (4224 + 5184)        // 5184 u32 (tf32 lo)
#define SM_HM   (4224 + 10368)       // 32*99 = 3168 floats (h-pooled conv out)
#define SM_SB2  (SM_HM + 3168)       // 32
#define SM_SRED (SM_SB2 + 32)        // 28
#define K2_SMEM_U32  (SM_SRED + 28 + 4)
#define K2_SMEM_BYTES (K2_SMEM_U32 * 4)

__global__ __launch_bounds__(256, 3) void k2_mma(
    const float* __restrict__ w2, const float* __restrict__ b2,
    const float* __restrict__ dw, const float* __restrict__ db)
{
    extern __shared__ uint32_t sm[];
    float*    sin_ = (float*)(sm + SM_SIN);
    uint32_t* AH   = sm + SM_AH;
    uint32_t* AL   = sm + SM_AL;
    float*    hmax = (float*)(sm + SM_HM);
    float*    sb2  = (float*)(sm + SM_SB2);
    float*    sred = (float*)(sm + SM_SRED);

    const int img = blockIdx.x;
    const int t = threadIdx.x;

    // --- prelude: input copy (restride 256 -> 264 floats per channel) ---
    {
        const u64* src = (const u64*)(g_h1 + (long)img * 4096);
        u64* dst = (u64*)sin_;
        for (int i = t; i < 2048; i += 256)
            dst[(i >> 7) * 132 + (i & 127)] = src[i];
    }
    // --- weights -> tf32 hi/lo, im2col K-order: k = tap*16 + ic ---
    for (int i = t; i < 4608; i += 256) {
        int oc = i / 144, r = i % 144;
        int ic = r / 9, tap = r % 9;
        float v = w2[i];
        uint32_t hi = f2tf32(v);
        uint32_t lo = f2tf32(v - __uint_as_float(hi));
        int k = tap * 16 + ic;
        int slot = (k >> 3) * 288 + (k & 7) * 36 + oc;
        AH[slot] = hi; AL[slot] = lo;
    }
    if (t < 32) sb2[t] = b2[t];
    __syncthreads();

    // --- main: warp-level mma ---
    const int lane = t & 31;
    const int wrp = t >> 5;
    const int q = lane & 3;          // k-quad / col pair index
    const int g = lane >> 2;         // row/col group index
    const int mt = wrp & 1;
    const int ocb = mt << 4;         // 0 or 16
    const int ntb = wrp >> 1;        // 0..3

    float c[7][4];
    int bpos[7];
#pragma unroll
    for (int j = 0; j < 7; j++) {
        c[j][0] = c[j][1] = c[j][2] = c[j][3] = 0.f;
        int nt = ntb + 4 * j;
        int n0 = nt * 8 + g;
        bpos[j] = (nt < 25 && n0 < 196) ? ((n0 / 14) * 16 + (n0 % 14)) : 0;
    }

#pragma unroll
    for (int ks = 0; ks < 18; ks++) {
        const int tap = ks >> 1;
        const int kr = tap / 3, kc = tap % 3;
        const int icb = (ks & 1) * 8;

        const int abase = ks * 288 + ocb + g;
        uint32_t ah0 = AH[abase + q * 36];
        uint32_t ah1 = AH[abase + q * 36 + 8];
        uint32_t ah2 = AH[abase + (q + 4) * 36];
        uint32_t ah3 = AH[abase + (q + 4) * 36 + 8];
        uint32_t al0 = AL[abase + q * 36];
        uint32_t al1 = AL[abase + q * 36 + 8];
        uint32_t al2 = AL[abase + (q + 4) * 36];
        uint32_t al3 = AL[abase + (q + 4) * 36 + 8];

        const int boff = (icb + q) * 264 + kr * 16 + kc;
#pragma unroll
        for (int j = 0; j < 7; j++) {
            if (ntb + 4 * j < 25) {
                float x0 = sin_[boff + bpos[j]];
                float x1 = sin_[boff + 4 * 264 + bpos[j]];
                uint32_t bh0 = f2tf32(x0);
                uint32_t bh1 = f2tf32(x1);
                uint32_t bl0 = f2tf32(x0 - __uint_as_float(bh0));
                uint32_t bl1 = f2tf32(x1 - __uint_as_float(bh1));
                mma_tf32(c[j], al0, al1, al2, al3, bh0, bh1);
                mma_tf32(c[j], ah0, ah1, ah2, ah3, bl0, bl1);
                mma_tf32(c[j], ah0, ah1, ah2, ah3, bh0, bh1);
            }
        }
    }

    // --- epilogue: horizontal pool pair (c0,c1)/(c2,c3) + bias -> hmax ---
    {
        const float bias0 = sb2[ocb + g];
        const float bias1 = sb2[ocb + g + 8];
#pragma unroll
        for (int j = 0; j < 7; j++) {
            int nt = ntb + 4 * j;
            if (nt < 25) {
                int n = nt * 8 + 2 * q;          // even -> x even -> pool pair
                if (n < 196) {
                    int y = n / 14, px = (n % 14) >> 1;
                    int hb = y * 7 + px;
                    hmax[(ocb + g) * 99 + hb]     = fmaxf(c[j][0], c[j][1]) + bias0;
                    hmax[(ocb + g + 8) * 99 + hb] = fmaxf(c[j][2], c[j][3]) + bias1;
                }
            }
        }
    }
    __syncthreads();

    // --- vertical pool + relu + dense (R4 epilogue) ---
    if (t < 224) {
        const int pr = t >> 5;   // pooled row (one per warp)
        const int ch = t & 31;   // channel (lane)
        float a4[4] = {0.f, 0.f, 0.f, 0.f};
#pragma unroll
        for (int px = 0; px < 7; px++) {
            float h0 = hmax[ch * 99 + (2 * pr) * 7 + px];
            float h1 = hmax[ch * 99 + (2 * pr + 1) * 7 + px];
            float pooled = fmaxf(fmaxf(h0, h1), 0.f);
            const int fi = ch * 49 + pr * 7 + px;
#pragma unroll
            for (int o = 0; o < 4; o++)
                a4[o] = fmaf(pooled, __ldg(&dw[o * 1568 + fi]), a4[o]);
        }
#pragma unroll
        for (int o = 0; o < 4; o++)
#pragma unroll
            for (int off = 16; off > 0; off >>= 1)
                a4[o] += __shfl_down_sync(0xffffffffu, a4[o], off);
        if (ch == 0) {
#pragma unroll
            for (int o = 0; o < 4; o++) sred[pr * 4 + o] = a4[o];
        }
    }
    __syncthreads();
    if (t < 4) {
        float s = db[t];
#pragma unroll
        for (int w = 0; w < 7; w++) s += sred[w * 4 + t];
        g_ang[img * 4 + t] = s;
    }
}

// ---------------------------------------------------------------------------
// Kernel 3: 4-qubit statevector sim + post linear. One thread per image.
// ---------------------------------------------------------------------------
__device__ __forceinline__ float2 cmul(float2 a, float2 b) {
    return make_float2(fmaf(a.x, b.x, -a.y * b.y), fmaf(a.x, b.y, a.y * b.x));
}

__device__ __forceinline__ void ap1(float2* s, int bit,
                                    float2 m00, float2 m01, float2 m10, float2 m11)
{
#pragma unroll
    for (int i = 0; i < 16; i++) {
        if (!(i & bit)) {
            const int i1 = i | bit;
            float2 a0 = s[i], a1 = s[i1];
            float2 r0, r1;
            r0.x = m00.x * a0.x - m00.y * a0.y + m01.x * a1.x - m01.y * a1.y;
            r0.y = m00.x * a0.y + m00.y * a0.x + m01.x * a1.y + m01.y * a1.x;
            r1.x = m10.x * a0.x - m10.y * a0.y + m11.x * a1.x - m11.y * a1.y;
            r1.y = m10.x * a0.y + m10.y * a0.x + m11.x * a1.y + m11.y * a1.x;
            s[i] = r0; s[i1] = r1;
        }
    }
}

__global__ __launch_bounds__(128) void k3_quantum_post(
    const float* __restrict__ qp, const float* __restrict__ pw,
    const float* __restrict__ pb, float* __restrict__ out, int B)
{
    const int img = blockIdx.x * blockDim.x + threadIdx.x;
    if (img >= B) return;

    float2 s[16];
#pragma unroll
    for (int i = 0; i < 16; i++) s[i] = make_float2(0.f, 0.f);
    s[0] = make_float2(1.f, 0.f);

#pragma unroll
    for (int w = 0; w < 4; w++) {
        const float th = g_ang[img * 4 + w] * 3.14159265358979323846f * 0.5f;
        float sn, cs;
        sincosf(th, &sn, &cs);
        ap1(s, 8 >> w, make_float2(cs, 0.f), make_float2(-sn, 0.f),
            make_float2(sn, 0.f), make_float2(cs, 0.f));
    }

    const int pc_[6] = {0, 0, 0, 1, 1, 2};
    const int pt_[6] = {1, 2, 3, 2, 3, 3};

#pragma unroll
    for (int l = 0; l < 2; l++) {
        const int st = l * 18;
#pragma unroll
        for (int q = 0; q < 4; q++) {
            float a = qp[st + q * 3 + 0];
            float b = qp[st + q * 3 + 1];
            float g = qp[st + q * 3 + 2];
            float sa, ca, sb, cb, sg, cg;
            sincosf(a * 0.5f, &sa, &ca);
            sincosf(b * 0.5f, &sb, &cb);
            sincosf(g * 0.5f, &sg, &cg);
            float2 m00 = make_float2(cb * ca,  sb * sa);
            float2 m01 = make_float2(-sb * ca, -cb * sa);
            float2 m10 = make_float2(sb * ca,  -cb * sa);
            float2 m11 = make_float2(cb * ca,  -sb * sa);
            const float2 em = make_float2(cg, -sg);
            const float2 ep = make_float2(cg,  sg);
            m00 = cmul(em, m00); m01 = cmul(em, m01);
            m10 = cmul(ep, m10); m11 = cmul(ep, m11);
            ap1(s, 8 >> q, m00, m01, m10, m11);
        }
#pragma unroll
        for (int k = 0; k < 6; k++) {
            const float phi = qp[st + 12 + k] * 0.5f;
            float sp, cp;
            sincosf(phi, &sp, &cp);
            const float2 em = make_float2(cp, -sp);
            const float2 ep = make_float2(cp,  sp);
            const int bc = 8 >> pc_[k];
            const int bt = 8 >> pt_[k];
#pragma unroll
            for (int base = 0; base < 16; base++) {
                if (!(base & (bc | bt))) {
                    const int i01 = base | bt, i10 = base | bc, i11 = base | bc | bt;
                    float2 t00 = s[base], t01 = s[i01], t10 = s[i10], t11 = s[i11];
                    s[base] = cmul(em, t00);
                    s[i01]  = cmul(ep, t01);
                    s[i10]  = cmul(em, t11);
                    s[i11]  = cmul(ep, t10);
                }
            }
        }
    }

    float z[4];
#pragma unroll
    for (int w = 0; w < 4; w++) {
        const int bit = 8 >> w;
        float zv = 0.f;
#pragma unroll
        for (int i = 0; i < 16; i++) {
            const float p = s[i].x * s[i].x + s[i].y * s[i].y;
            zv += (i & bit) ? -p : p;
        }
        z[w] = zv;
    }

#pragma unroll
    for (int k = 0; k < 10; k++) {
        float o = pb[k];
#pragma unroll
        for (int j = 0; j < 4; j++) o = fmaf(z[j], pw[k * 4 + j], o);
        out[img * 10 + k] = o;
    }
}

// ---------------------------------------------------------------------------
extern "C" void kernel_launch(void* const* d_in, const int* in_sizes, int n_in,
                              void* d_out, int out_size)
{
    const float* x    = (const float*)d_in[0];
    const float* c1w  = (const float*)d_in[1];
    const float* c1b  = (const float*)d_in[2];
    const float* c2w  = (const float*)d_in[3];
    const float* c2b  = (const float*)d_in[4];
    const float* dw   = (const float*)d_in[5];
    const float* db   = (const float*)d_in[6];
    const float* qp   = (const float*)d_in[7];
    const float* pw   = (const float*)d_in[8];
    const float* pb   = (const float*)d_in[9];
    float* out = (float*)d_out;

    int B = in_sizes[0] / 784;
    if (B > B_MAX) B = B_MAX;

    cudaFuncSetAttribute(k2_mma,
                         cudaFuncAttributeMaxDynamicSharedMemorySize,
                         K2_SMEM_BYTES);

    k1_conv1<<<B, 196>>>(x, c1w, c1b);
    k2_mma<<<B, 256, K2_SMEM_BYTES>>>(c2w, c2b, dw, db);
    k3_quantum_post<<<(B + 127) / 128, 128>>>(qp, pw, pb, out, B);
}

// round 13
// speedup vs baseline: 1.0072x; 1.0072x over previous
#include <cuda_runtime.h>
#include <math.h>
#include <stdint.h>

#define B_MAX 4096

typedef unsigned long long u64;

// Scratch: conv1 pooled output in k2-ready padded layout [B][16ch][16][16]
// (row/col 0 and 15 are zero borders), plus dense angles [B][4].
__device__ float g_h1[B_MAX * 4096];
__device__ float g_ang[B_MAX * 4];

// ---------------------------------------------------------------------------
// f32x2 packed-FMA helpers (k1 only)
// ---------------------------------------------------------------------------
__device__ __forceinline__ u64 pack2(float lo, float hi) {
    u64 r; asm("mov.b64 %0, {%1,%2};" : "=l"(r) : "f"(lo), "f"(hi)); return r;
}
__device__ __forceinline__ void unpack2(u64 v, float& lo, float& hi) {
    asm("mov.b64 {%0,%1}, %2;" : "=f"(lo), "=f"(hi) : "l"(v));
}
__device__ __forceinline__ u64 ffma2(u64 a, u64 b, u64 c) {
    u64 d; asm("fma.rn.f32x2 %0, %1, %2, %3;" : "=l"(d) : "l"(a), "l"(b), "l"(c));
    return d;
}

// ---------------------------------------------------------------------------
// tf32 helpers
// ---------------------------------------------------------------------------
__device__ __forceinline__ uint32_t f2tf32(float x) {
    uint32_t r; asm("cvt.rna.tf32.f32 %0, %1;" : "=r"(r) : "f"(x)); return r;
}
__device__ __forceinline__ void mma_tf32(float c[4],
    uint32_t a0, uint32_t a1, uint32_t a2, uint32_t a3,
    uint32_t b0, uint32_t b1)
{
    asm volatile(
        "mma.sync.aligned.m16n8k8.row.col.f32.tf32.tf32.f32 "
        "{%0,%1,%2,%3}, {%4,%5,%6,%7}, {%8,%9}, {%0,%1,%2,%3};"
        : "+f"(c[0]), "+f"(c[1]), "+f"(c[2]), "+f"(c[3])
        : "r"(a0), "r"(a1), "r"(a2), "r"(a3), "r"(b0), "r"(b1));
}

// ---------------------------------------------------------------------------
// Kernel 1: conv1 (1->16) + ReLU + 2x2 pool. [R4 version — measured 34.2us]
// ---------------------------------------------------------------------------
#define K1S 34

__global__ __launch_bounds__(196, 4) void k1_conv1(
    const float* __restrict__ x, const float* __restrict__ w,
    const float* __restrict__ b)
{
    __shared__ float sxp[30 * K1S];   // zero-padded 30x30 input
    __shared__ u64 swp[80];           // [8 cg][9] packed weights + [8] packed bias

    const int img = blockIdx.x;
    const int t = threadIdx.x;
    const float* xi = x + img * 784;

    for (int i = t; i < 30 * K1S; i += 196) sxp[i] = 0.f;
    if (t < 72)      swp[t] = pack2(w[t], w[t + 72]);          // cg=t/9,k=t%9
    else if (t < 80) swp[t] = pack2(b[t - 72], b[t - 64]);
    __syncthreads();
#pragma unroll
    for (int k = 0; k < 4; k++) {                 // 784 = 4*196 exactly
        int i = t + k * 196;
        int r = i / 28, c = i % 28;
        sxp[(r + 1) * K1S + (c + 1)] = xi[i];
    }
    __syncthreads();

    const int pr = t / 14;
    const int pc = t % 14;

    u64 pv[16];
    {
        const float* p0 = &sxp[(2 * pr) * K1S + 2 * pc];
#pragma unroll
        for (int j = 0; j < 4; j++) {
            float2 a  = *(const float2*)(p0 + j * K1S);
            float2 bq = *(const float2*)(p0 + j * K1S + 2);
            pv[j * 4 + 0] = pack2(a.x, a.x);
            pv[j * 4 + 1] = pack2(a.y, a.y);
            pv[j * 4 + 2] = pack2(bq.x, bq.x);
            pv[j * 4 + 3] = pack2(bq.y, bq.y);
        }
    }

    float* outp = g_h1 + (long)img * 4096 + (pr + 1) * 16 + (pc + 1);

#pragma unroll
    for (int cg = 0; cg < 8; cg++) {
        u64 wp[9];
#pragma unroll
        for (int k = 0; k < 9; k++) wp[k] = swp[cg * 9 + k];
        const u64 bb = swp[72 + cg];
        u64 acc[4] = {bb, bb, bb, bb};
#pragma unroll
        for (int kr = 0; kr < 3; kr++)
#pragma unroll
            for (int kc = 0; kc < 3; kc++) {
                const u64 wv = wp[kr * 3 + kc];
#pragma unroll
                for (int dr = 0; dr < 2; dr++)
#pragma unroll
                    for (int dc = 0; dc < 2; dc++)
                        acc[dr * 2 + dc] =
                            ffma2(pv[(dr + kr) * 4 + (dc + kc)], wv, acc[dr * 2 + dc]);
            }
        float l0, h0, l1, h1, l2, h2, l3, h3;
        unpack2(acc[0], l0, h0); unpack2(acc[1], l1, h1);
        unpack2(acc[2], l2, h2); unpack2(acc[3], l3, h3);
        float mlo = fmaxf(fmaxf(fmaxf(l0, l1), fmaxf(l2, l3)), 0.f);
        float mhi = fmaxf(fmaxf(fmaxf(h0, h1), fmaxf(h2, h3)), 0.f);
        outp[cg * 256]       = mlo;
        outp[(cg + 8) * 256] = mhi;
    }

    for (int i = t; i < 960; i += 196) {
        int ch = i / 60, j = i % 60;
        int r, c;
        if (j < 16)      { r = 0;  c = j; }
        else if (j < 32) { r = 15; c = j - 16; }
        else if (j < 46) { r = j - 31; c = 0; }
        else             { r = j - 45; c = 15; }
        g_h1[(long)img * 4096 + ch * 256 + r * 16 + c] = 0.f;
    }
}

// ---------------------------------------------------------------------------
// Kernel 2: conv2 as implicit-GEMM tf32 tensor-core (3xTF32) + pool + dense.
// One image per CTA, 256 threads = 8 warps. Warp w: m-tile = w&1 (16 ocs),
// n-tiles = (w>>1) + 4j (8 positions each, N=196 padded to 200).
// K = 144 = 9 taps x 16 ic, 18 k-steps of 8. B gathered from padded smem
// tile (channel stride 264 -> conflict-free fragment loads).
// ---------------------------------------------------------------------------
#define SM_SIN  0                    // 16*264 = 4224 floats
#define SM_AH   4224                 // 18*288 = 5184 u32 (tf32 hi)
#define SM_AL   (4224 + 5184)        // 5184 u32 (tf32 lo)
#define SM_HM   (4224 + 10368)       // 32*99 = 3168 floats (h-pooled conv out)
#define SM_SB2  (SM_HM + 3168)       // 32
#define SM_SRED (SM_SB2 + 32)        // 28
#define K2_SMEM_U32  (SM_SRED + 28 + 4)
#define K2_SMEM_BYTES (K2_SMEM_U32 * 4)

__global__ __launch_bounds__(256, 3) void k2_mma(
    const float* __restrict__ w2, const float* __restrict__ b2,
    const float* __restrict__ dw, const float* __restrict__ db)
{
    extern __shared__ uint32_t sm[];
    float*    sin_ = (float*)(sm + SM_SIN);
    uint32_t* AH   = sm + SM_AH;
    uint32_t* AL   = sm + SM_AL;
    float*    hmax = (float*)(sm + SM_HM);
    float*    sb2  = (float*)(sm + SM_SB2);
    float*    sred = (float*)(sm + SM_SRED);

    const int img = blockIdx.x;
    const int t = threadIdx.x;

    // --- prelude: input copy (restride 256 -> 264 floats per channel) ---
    {
        const u64* src = (const u64*)(g_h1 + (long)img * 4096);
        u64* dst = (u64*)sin_;
        for (int i = t; i < 2048; i += 256)
            dst[(i >> 7) * 132 + (i & 127)] = src[i];
    }
    // --- weights -> tf32 hi/lo, im2col K-order: k = tap*16 + ic ---
    for (int i = t; i < 4608; i += 256) {
        int oc = i / 144, r = i % 144;
        int ic = r / 9, tap = r % 9;
        float v = w2[i];
        uint32_t hi = f2tf32(v);
        uint32_t lo = f2tf32(v - __uint_as_float(hi));
        int k = tap * 16 + ic;
        int slot = (k >> 3) * 288 + (k & 7) * 36 + oc;
        AH[slot] = hi; AL[slot] = lo;
    }
    if (t < 32) sb2[t] = b2[t];
    __syncthreads();

    // --- main: warp-level mma ---
    const int lane = t & 31;
    const int wrp = t >> 5;
    const int q = lane & 3;          // k-quad / col pair index
    const int g = lane >> 2;         // row/col group index
    const int mt = wrp & 1;
    const int ocb = mt << 4;         // 0 or 16
    const int ntb = wrp >> 1;        // 0..3

    float c[7][4];
    int bpos[7];
#pragma unroll
    for (int j = 0; j < 7; j++) {
        c[j][0] = c[j][1] = c[j][2] = c[j][3] = 0.f;
        int nt = ntb + 4 * j;
        int n0 = nt * 8 + g;
        bpos[j] = (nt < 25 && n0 < 196) ? ((n0 / 14) * 16 + (n0 % 14)) : 0;
    }

#pragma unroll
    for (int ks = 0; ks < 18; ks++) {
        const int tap = ks >> 1;
        const int kr = tap / 3, kc = tap % 3;
        const int icb = (ks & 1) * 8;

        const int abase = ks * 288 + ocb + g;
        uint32_t ah0 = AH[abase + q * 36];
        uint32_t ah1 = AH[abase + q * 36 + 8];
        uint32_t ah2 = AH[abase + (q + 4) * 36];
        uint32_t ah3 = AH[abase + (q + 4) * 36 + 8];
        uint32_t al0 = AL[abase + q * 36];
        uint32_t al1 = AL[abase + q * 36 + 8];
        uint32_t al2 = AL[abase + (q + 4) * 36];
        uint32_t al3 = AL[abase + (q + 4) * 36 + 8];

        const int boff = (icb + q) * 264 + kr * 16 + kc;
#pragma unroll
        for (int j = 0; j < 7; j++) {
            if (ntb + 4 * j < 25) {
                float x0 = sin_[boff + bpos[j]];
                float x1 = sin_[boff + 4 * 264 + bpos[j]];
                uint32_t bh0 = f2tf32(x0);
                uint32_t bh1 = f2tf32(x1);
                uint32_t bl0 = f2tf32(x0 - __uint_as_float(bh0));
                uint32_t bl1 = f2tf32(x1 - __uint_as_float(bh1));
                mma_tf32(c[j], al0, al1, al2, al3, bh0, bh1);
                mma_tf32(c[j], ah0, ah1, ah2, ah3, bl0, bl1);
                mma_tf32(c[j], ah0, ah1, ah2, ah3, bh0, bh1);
            }
        }
    }

    // --- epilogue: horizontal pool pair (c0,c1)/(c2,c3) + bias -> hmax ---
    {
        const float bias0 = sb2[ocb + g];
        const float bias1 = sb2[ocb + g + 8];
#pragma unroll
        for (int j = 0; j < 7; j++) {
            int nt = ntb + 4 * j;
            if (nt < 25) {
                int n = nt * 8 + 2 * q;          // even -> x even -> pool pair
                if (n < 196) {
                    int y = n / 14, px = (n % 14) >> 1;
                    int hb = y * 7 + px;
                    hmax[(ocb + g) * 99 + hb]     = fmaxf(c[j][0], c[j][1]) + bias0;
                    hmax[(ocb + g + 8) * 99 + hb] = fmaxf(c[j][2], c[j][3]) + bias1;
                }
            }
        }
    }
    __syncthreads();

    // --- vertical pool + relu + dense (R4 epilogue) ---
    if (t < 224) {
        const int pr = t >> 5;   // pooled row (one per warp)
        const int ch = t & 31;   // channel (lane)
        float a4[4] = {0.f, 0.f, 0.f, 0.f};
#pragma unroll
        for (int px = 0; px < 7; px++) {
            float h0 = hmax[ch * 99 + (2 * pr) * 7 + px];
            float h1 = hmax[ch * 99 + (2 * pr + 1) * 7 + px];
            float pooled = fmaxf(fmaxf(h0, h1), 0.f);
            const int fi = ch * 49 + pr * 7 + px;
#pragma unroll
            for (int o = 0; o < 4; o++)
                a4[o] = fmaf(pooled, __ldg(&dw[o * 1568 + fi]), a4[o]);
        }
#pragma unroll
        for (int o = 0; o < 4; o++)
#pragma unroll
            for (int off = 16; off > 0; off >>= 1)
                a4[o] += __shfl_down_sync(0xffffffffu, a4[o], off);
        if (ch == 0) {
#pragma unroll
            for (int o = 0; o < 4; o++) sred[pr * 4 + o] = a4[o];
        }
    }
    __syncthreads();
    if (t < 4) {
        float s = db[t];
#pragma unroll
        for (int w = 0; w < 7; w++) s += sred[w * 4 + t];
        g_ang[img * 4 + t] = s;
    }
}

// ---------------------------------------------------------------------------
// Kernel 3: 4-qubit statevector sim + post linear. One thread per image.
// ---------------------------------------------------------------------------
__device__ __forceinline__ float2 cmul(float2 a, float2 b) {
    return make_float2(fmaf(a.x, b.x, -a.y * b.y), fmaf(a.x, b.y, a.y * b.x));
}

__device__ __forceinline__ void ap1(float2* s, int bit,
                                    float2 m00, float2 m01, float2 m10, float2 m11)
{
#pragma unroll
    for (int i = 0; i < 16; i++) {
        if (!(i & bit)) {
            const int i1 = i | bit;
            float2 a0 = s[i], a1 = s[i1];
            float2 r0, r1;
            r0.x = m00.x * a0.x - m00.y * a0.y + m01.x * a1.x - m01.y * a1.y;
            r0.y = m00.x * a0.y + m00.y * a0.x + m01.x * a1.y + m01.y * a1.x;
            r1.x = m10.x * a0.x - m10.y * a0.y + m11.x * a1.x - m11.y * a1.y;
            r1.y = m10.x * a0.y + m10.y * a0.x + m11.x * a1.y + m11.y * a1.x;
            s[i] = r0; s[i1] = r1;
        }
    }
}

__global__ __launch_bounds__(128) void k3_quantum_post(
    const float* __restrict__ qp, const float* __restrict__ pw,
    const float* __restrict__ pb, float* __restrict__ out, int B)
{
    const int img = blockIdx.x * blockDim.x + threadIdx.x;
    if (img >= B) return;

    float2 s[16];
#pragma unroll
    for (int i = 0; i < 16; i++) s[i] = make_float2(0.f, 0.f);
    s[0] = make_float2(1.f, 0.f);

#pragma unroll
    for (int w = 0; w < 4; w++) {
        const float th = g_ang[img * 4 + w] * 3.14159265358979323846f * 0.5f;
        float sn, cs;
        sincosf(th, &sn, &cs);
        ap1(s, 8 >> w, make_float2(cs, 0.f), make_float2(-sn, 0.f),
            make_float2(sn, 0.f), make_float2(cs, 0.f));
    }

    const int pc_[6] = {0, 0, 0, 1, 1, 2};
    const int pt_[6] = {1, 2, 3, 2, 3, 3};

#pragma unroll
    for (int l = 0; l < 2; l++) {
        const int st = l * 18;
#pragma unroll
        for (int q = 0; q < 4; q++) {
            float a = qp[st + q * 3 + 0];
            float b = qp[st + q * 3 + 1];
            float g = qp[st + q * 3 + 2];
            float sa, ca, sb, cb, sg, cg;
            sincosf(a * 0.5f, &sa, &ca);
            sincosf(b * 0.5f, &sb, &cb);
            sincosf(g * 0.5f, &sg, &cg);
            float2 m00 = make_float2(cb * ca,  sb * sa);
            float2 m01 = make_float2(-sb * ca, -cb * sa);
            float2 m10 = make_float2(sb * ca,  -cb * sa);
            float2 m11 = make_float2(cb * ca,  -sb * sa);
            const float2 em = make_float2(cg, -sg);
            const float2 ep = make_float2(cg,  sg);
            m00 = cmul(em, m00); m01 = cmul(em, m01);
            m10 = cmul(ep, m10); m11 = cmul(ep, m11);
            ap1(s, 8 >> q, m00, m01, m10, m11);
        }
#pragma unroll
        for (int k = 0; k < 6; k++) {
            const float phi = qp[st + 12 + k] * 0.5f;
            float sp, cp;
            sincosf(phi, &sp, &cp);
            const float2 em = make_float2(cp, -sp);
            const float2 ep = make_float2(cp,  sp);
            const int bc = 8 >> pc_[k];
            const int bt = 8 >> pt_[k];
#pragma unroll
            for (int base = 0; base < 16; base++) {
                if (!(base & (bc | bt))) {
                    const int i01 = base | bt, i10 = base | bc, i11 = base | bc | bt;
                    float2 t00 = s[base], t01 = s[i01], t10 = s[i10], t11 = s[i11];
                    s[base] = cmul(em, t00);
                    s[i01]  = cmul(ep, t01);
                    s[i10]  = cmul(em, t11);
                    s[i11]  = cmul(ep, t10);
                }
            }
        }
    }

    float z[4];
#pragma unroll
    for (int w = 0; w < 4; w++) {
        const int bit = 8 >> w;
        float zv = 0.f;
#pragma unroll
        for (int i = 0; i < 16; i++) {
            const float p = s[i].x * s[i].x + s[i].y * s[i].y;
            zv += (i & bit) ? -p : p;
        }
        z[w] = zv;
    }

#pragma unroll
    for (int k = 0; k < 10; k++) {
        float o = pb[k];
#pragma unroll
        for (int j = 0; j < 4; j++) o = fmaf(z[j], pw[k * 4 + j], o);
        out[img * 10 + k] = o;
    }
}

// ---------------------------------------------------------------------------
extern "C" void kernel_launch(void* const* d_in, const int* in_sizes, int n_in,
                              void* d_out, int out_size)
{
    const float* x    = (const float*)d_in[0];
    const float* c1w  = (const float*)d_in[1];
    const float* c1b  = (const float*)d_in[2];
    const float* c2w  = (const float*)d_in[3];
    const float* c2b  = (const float*)d_in[4];
    const float* dw   = (const float*)d_in[5];
    const float* db   = (const float*)d_in[6];
    const float* qp   = (const float*)d_in[7];
    const float* pw   = (const float*)d_in[8];
    const float* pb   = (const float*)d_in[9];
    float* out = (float*)d_out;

    int B = in_sizes[0] / 784;
    if (B > B_MAX) B = B_MAX;

    cudaFuncSetAttribute(k2_mma,
                         cudaFuncAttributeMaxDynamicSharedMemorySize,
                         K2_SMEM_BYTES);

    k1_conv1<<<B, 196>>>(x, c1w, c1b);
    k2_mma<<<B, 256, K2_SMEM_BYTES>>>(c2w, c2b, dw, db);
    k3_quantum_post<<<(B + 127) / 128, 128>>>(qp, pw, pb, out, B);
}

// round 14
// speedup vs baseline: 1.0094x; 1.0023x over previous
#include <cuda_runtime.h>
#include <math.h>
#include <stdint.h>

#define B_MAX 4096

typedef unsigned long long u64;

// Scratch: conv1 pooled output in k2-ready padded layout [B][16ch][16][16]
// (row/col 0 and 15 are zero borders), plus dense angles [B][4].
__device__ float g_h1[B_MAX * 4096];
__device__ float g_ang[B_MAX * 4];

// ---------------------------------------------------------------------------
// f32x2 packed-FMA helpers (k1 only)
// ---------------------------------------------------------------------------
__device__ __forceinline__ u64 pack2(float lo, float hi) {
    u64 r; asm("mov.b64 %0, {%1,%2};" : "=l"(r) : "f"(lo), "f"(hi)); return r;
}
__device__ __forceinline__ void unpack2(u64 v, float& lo, float& hi) {
    asm("mov.b64 {%0,%1}, %2;" : "=f"(lo), "=f"(hi) : "l"(v));
}
__device__ __forceinline__ u64 ffma2(u64 a, u64 b, u64 c) {
    u64 d; asm("fma.rn.f32x2 %0, %1, %2, %3;" : "=l"(d) : "l"(a), "l"(b), "l"(c));
    return d;
}

// ---------------------------------------------------------------------------
// tf32 helpers
// ---------------------------------------------------------------------------
__device__ __forceinline__ uint32_t f2tf32(float x) {
    uint32_t r; asm("cvt.rna.tf32.f32 %0, %1;" : "=r"(r) : "f"(x)); return r;
}
__device__ __forceinline__ void mma_tf32(float c[4],
    uint32_t a0, uint32_t a1, uint32_t a2, uint32_t a3,
    uint32_t b0, uint32_t b1)
{
    asm volatile(
        "mma.sync.aligned.m16n8k8.row.col.f32.tf32.tf32.f32 "
        "{%0,%1,%2,%3}, {%4,%5,%6,%7}, {%8,%9}, {%0,%1,%2,%3};"
        : "+f"(c[0]), "+f"(c[1]), "+f"(c[2]), "+f"(c[3])
        : "r"(a0), "r"(a1), "r"(a2), "r"(a3), "r"(b0), "r"(b1));
}

// ---------------------------------------------------------------------------
// Kernel 1: conv1 (1->16) + ReLU + 2x2 pool. [R4 version — measured 34.2us]
// ---------------------------------------------------------------------------
#define K1S 34

__global__ __launch_bounds__(196, 4) void k1_conv1(
    const float* __restrict__ x, const float* __restrict__ w,
    const float* __restrict__ b)
{
    __shared__ float sxp[30 * K1S];   // zero-padded 30x30 input
    __shared__ u64 swp[80];           // [8 cg][9] packed weights + [8] packed bias

    const int img = blockIdx.x;
    const int t = threadIdx.x;
    const float* xi = x + img * 784;

    for (int i = t; i < 30 * K1S; i += 196) sxp[i] = 0.f;
    if (t < 72)      swp[t] = pack2(w[t], w[t + 72]);          // cg=t/9,k=t%9
    else if (t < 80) swp[t] = pack2(b[t - 72], b[t - 64]);
    __syncthreads();
#pragma unroll
    for (int k = 0; k < 4; k++) {                 // 784 = 4*196 exactly
        int i = t + k * 196;
        int r = i / 28, c = i % 28;
        sxp[(r + 1) * K1S + (c + 1)] = xi[i];
    }
    __syncthreads();

    const int pr = t / 14;
    const int pc = t % 14;

    u64 pv[16];
    {
        const float* p0 = &sxp[(2 * pr) * K1S + 2 * pc];
#pragma unroll
        for (int j = 0; j < 4; j++) {
            float2 a  = *(const float2*)(p0 + j * K1S);
            float2 bq = *(const float2*)(p0 + j * K1S + 2);
            pv[j * 4 + 0] = pack2(a.x, a.x);
            pv[j * 4 + 1] = pack2(a.y, a.y);
            pv[j * 4 + 2] = pack2(bq.x, bq.x);
            pv[j * 4 + 3] = pack2(bq.y, bq.y);
        }
    }

    float* outp = g_h1 + (long)img * 4096 + (pr + 1) * 16 + (pc + 1);

#pragma unroll
    for (int cg = 0; cg < 8; cg++) {
        u64 wp[9];
#pragma unroll
        for (int k = 0; k < 9; k++) wp[k] = swp[cg * 9 + k];
        const u64 bb = swp[72 + cg];
        u64 acc[4] = {bb, bb, bb, bb};
#pragma unroll
        for (int kr = 0; kr < 3; kr++)
#pragma unroll
            for (int kc = 0; kc < 3; kc++) {
                const u64 wv = wp[kr * 3 + kc];
#pragma unroll
                for (int dr = 0; dr < 2; dr++)
#pragma unroll
                    for (int dc = 0; dc < 2; dc++)
                        acc[dr * 2 + dc] =
                            ffma2(pv[(dr + kr) * 4 + (dc + kc)], wv, acc[dr * 2 + dc]);
            }
        float l0, h0, l1, h1, l2, h2, l3, h3;
        unpack2(acc[0], l0, h0); unpack2(acc[1], l1, h1);
        unpack2(acc[2], l2, h2); unpack2(acc[3], l3, h3);
        float mlo = fmaxf(fmaxf(fmaxf(l0, l1), fmaxf(l2, l3)), 0.f);
        float mhi = fmaxf(fmaxf(fmaxf(h0, h1), fmaxf(h2, h3)), 0.f);
        outp[cg * 256]       = mlo;
        outp[(cg + 8) * 256] = mhi;
    }

    for (int i = t; i < 960; i += 196) {
        int ch = i / 60, j = i % 60;
        int r, c;
        if (j < 16)      { r = 0;  c = j; }
        else if (j < 32) { r = 15; c = j - 16; }
        else if (j < 46) { r = j - 31; c = 0; }
        else             { r = j - 45; c = 15; }
        g_h1[(long)img * 4096 + ch * 256 + r * 16 + c] = 0.f;
    }
}

// ---------------------------------------------------------------------------
// Kernel 2: conv2 as implicit-GEMM tf32 tensor-core (3xTF32) + pool + dense.
// One image per CTA, 256 threads = 8 warps. Warp w: m-tile = w&1 (16 ocs),
// n-tiles = (w>>1) + 4j (8 positions each, N=196 padded to 200).
// K = 144 = 9 taps x 16 ic, 18 k-steps of 8. B gathered from padded smem
// tile (channel stride 264 -> conflict-free fragment loads).
// ---------------------------------------------------------------------------
#define SM_SIN  0                    // 16*264 = 4224 floats
#define SM_AH   4224                 // 18*288 = 5184 u32 (tf32 hi)
#define SM_AL   (4224 + 5184)        // 5184 u32 (tf32 lo)
#define SM_HM   (4224 + 10368)       // 32*99 = 3168 floats (h-pooled conv out)
#define SM_SB2  (SM_HM + 3168)       // 32
#define SM_SRED (SM_SB2 + 32)        // 28
#define K2_SMEM_U32  (SM_SRED + 28 + 4)
#define K2_SMEM_BYTES (K2_SMEM_U32 * 4)

__global__ __launch_bounds__(256, 3) void k2_mma(
    const float* __restrict__ w2, const float* __restrict__ b2,
    const float* __restrict__ dw, const float* __restrict__ db)
{
    extern __shared__ uint32_t sm[];
    float*    sin_ = (float*)(sm + SM_SIN);
    uint32_t* AH   = sm + SM_AH;
    uint32_t* AL   = sm + SM_AL;
    float*    hmax = (float*)(sm + SM_HM);
    float*    sb2  = (float*)(sm + SM_SB2);
    float*    sred = (float*)(sm + SM_SRED);

    const int img = blockIdx.x;
    const int t = threadIdx.x;

    // --- prelude: input copy (restride 256 -> 264 floats per channel) ---
    {
        const u64* src = (const u64*)(g_h1 + (long)img * 4096);
        u64* dst = (u64*)sin_;
        for (int i = t; i < 2048; i += 256)
            dst[(i >> 7) * 132 + (i & 127)] = src[i];
    }
    // --- weights -> tf32 hi/lo, im2col K-order: k = tap*16 + ic ---
    for (int i = t; i < 4608; i += 256) {
        int oc = i / 144, r = i % 144;
        int ic = r / 9, tap = r % 9;
        float v = w2[i];
        uint32_t hi = f2tf32(v);
        uint32_t lo = f2tf32(v - __uint_as_float(hi));
        int k = tap * 16 + ic;
        int slot = (k >> 3) * 288 + (k & 7) * 36 + oc;
        AH[slot] = hi; AL[slot] = lo;
    }
    if (t < 32) sb2[t] = b2[t];
    __syncthreads();

    // --- main: warp-level mma ---
    const int lane = t & 31;
    const int wrp = t >> 5;
    const int q = lane & 3;          // k-quad / col pair index
    const int g = lane >> 2;         // row/col group index
    const int mt = wrp & 1;
    const int ocb = mt << 4;         // 0 or 16
    const int ntb = wrp >> 1;        // 0..3

    float c[7][4];
    int bpos[7];
#pragma unroll
    for (int j = 0; j < 7; j++) {
        c[j][0] = c[j][1] = c[j][2] = c[j][3] = 0.f;
        int nt = ntb + 4 * j;
        int n0 = nt * 8 + g;
        bpos[j] = (nt < 25 && n0 < 196) ? ((n0 / 14) * 16 + (n0 % 14)) : 0;
    }

#pragma unroll
    for (int ks = 0; ks < 18; ks++) {
        const int tap = ks >> 1;
        const int kr = tap / 3, kc = tap % 3;
        const int icb = (ks & 1) * 8;

        const int abase = ks * 288 + ocb + g;
        uint32_t ah0 = AH[abase + q * 36];
        uint32_t ah1 = AH[abase + q * 36 + 8];
        uint32_t ah2 = AH[abase + (q + 4) * 36];
        uint32_t ah3 = AH[abase + (q + 4) * 36 + 8];
        uint32_t al0 = AL[abase + q * 36];
        uint32_t al1 = AL[abase + q * 36 + 8];
        uint32_t al2 = AL[abase + (q + 4) * 36];
        uint32_t al3 = AL[abase + (q + 4) * 36 + 8];

        const int boff = (icb + q) * 264 + kr * 16 + kc;
#pragma unroll
        for (int j = 0; j < 7; j++) {
            if (ntb + 4 * j < 25) {
                float x0 = sin_[boff + bpos[j]];
                float x1 = sin_[boff + 4 * 264 + bpos[j]];
                uint32_t bh0 = f2tf32(x0);
                uint32_t bh1 = f2tf32(x1);
                uint32_t bl0 = f2tf32(x0 - __uint_as_float(bh0));
                uint32_t bl1 = f2tf32(x1 - __uint_as_float(bh1));
                mma_tf32(c[j], al0, al1, al2, al3, bh0, bh1);
                mma_tf32(c[j], ah0, ah1, ah2, ah3, bl0, bl1);
                mma_tf32(c[j], ah0, ah1, ah2, ah3, bh0, bh1);
            }
        }
    }

    // --- epilogue: horizontal pool pair (c0,c1)/(c2,c3) + bias -> hmax ---
    {
        const float bias0 = sb2[ocb + g];
        const float bias1 = sb2[ocb + g + 8];
#pragma unroll
        for (int j = 0; j < 7; j++) {
            int nt = ntb + 4 * j;
            if (nt < 25) {
                int n = nt * 8 + 2 * q;          // even -> x even -> pool pair
                if (n < 196) {
                    int y = n / 14, px = (n % 14) >> 1;
                    int hb = y * 7 + px;
                    hmax[(ocb + g) * 99 + hb]     = fmaxf(c[j][0], c[j][1]) + bias0;
                    hmax[(ocb + g + 8) * 99 + hb] = fmaxf(c[j][2], c[j][3]) + bias1;
                }
            }
        }
    }
    __syncthreads();

    // --- vertical pool + relu + dense (R4 epilogue) ---
    if (t < 224) {
        const int pr = t >> 5;   // pooled row (one per warp)
        const int ch = t & 31;   // channel (lane)
        float a4[4] = {0.f, 0.f, 0.f, 0.f};
#pragma unroll
        for (int px = 0; px < 7; px++) {
            float h0 = hmax[ch * 99 + (2 * pr) * 7 + px];
            float h1 = hmax[ch * 99 + (2 * pr + 1) * 7 + px];
            float pooled = fmaxf(fmaxf(h0, h1), 0.f);
            const int fi = ch * 49 + pr * 7 + px;
#pragma unroll
            for (int o = 0; o < 4; o++)
                a4[o] = fmaf(pooled, __ldg(&dw[o * 1568 + fi]), a4[o]);
        }
#pragma unroll
        for (int o = 0; o < 4; o++)
#pragma unroll
            for (int off = 16; off > 0; off >>= 1)
                a4[o] += __shfl_down_sync(0xffffffffu, a4[o], off);
        if (ch == 0) {
#pragma unroll
            for (int o = 0; o < 4; o++) sred[pr * 4 + o] = a4[o];
        }
    }
    __syncthreads();
    if (t < 4) {
        float s = db[t];
#pragma unroll
        for (int w = 0; w < 7; w++) s += sred[w * 4 + t];
        g_ang[img * 4 + t] = s;
    }
}

// ---------------------------------------------------------------------------
// Kernel 3: 4-qubit statevector sim + post linear. One thread per image.
// ---------------------------------------------------------------------------
__device__ __forceinline__ float2 cmul(float2 a, float2 b) {
    return make_float2(fmaf(a.x, b.x, -a.y * b.y), fmaf(a.x, b.y, a.y * b.x));
}

__device__ __forceinline__ void ap1(float2* s, int bit,
                                    float2 m00, float2 m01, float2 m10, float2 m11)
{
#pragma unroll
    for (int i = 0; i < 16; i++) {
        if (!(i & bit)) {
            const int i1 = i | bit;
            float2 a0 = s[i], a1 = s[i1];
            float2 r0, r1;
            r0.x = m00.x * a0.x - m00.y * a0.y + m01.x * a1.x - m01.y * a1.y;
            r0.y = m00.x * a0.y + m00.y * a0.x + m01.x * a1.y + m01.y * a1.x;
            r1.x = m10.x * a0.x - m10.y * a0.y + m11.x * a1.x - m11.y * a1.y;
            r1.y = m10.x * a0.y + m10.y * a0.x + m11.x * a1.y + m11.y * a1.x;
            s[i] = r0; s[i1] = r1;
        }
    }
}

__global__ __launch_bounds__(128) void k3_quantum_post(
    const float* __restrict__ qp, const float* __restrict__ pw,
    const float* __restrict__ pb, float* __restrict__ out, int B)
{
    const int img = blockIdx.x * blockDim.x + threadIdx.x;
    if (img >= B) return;

    float2 s[16];
#pragma unroll
    for (int i = 0; i < 16; i++) s[i] = make_float2(0.f, 0.f);
    s[0] = make_float2(1.f, 0.f);

#pragma unroll
    for (int w = 0; w < 4; w++) {
        const float th = g_ang[img * 4 + w] * 3.14159265358979323846f * 0.5f;
        float sn, cs;
        sincosf(th, &sn, &cs);
        ap1(s, 8 >> w, make_float2(cs, 0.f), make_float2(-sn, 0.f),
            make_float2(sn, 0.f), make_float2(cs, 0.f));
    }

    const int pc_[6] = {0, 0, 0, 1, 1, 2};
    const int pt_[6] = {1, 2, 3, 2, 3, 3};

#pragma unroll
    for (int l = 0; l < 2; l++) {
        const int st = l * 18;
#pragma unroll
        for (int q = 0; q < 4; q++) {
            float a = qp[st + q * 3 + 0];
            float b = qp[st + q * 3 + 1];
            float g = qp[st + q * 3 + 2];
            float sa, ca, sb, cb, sg, cg;
            sincosf(a * 0.5f, &sa, &ca);
            sincosf(b * 0.5f, &sb, &cb);
            sincosf(g * 0.5f, &sg, &cg);
            float2 m00 = make_float2(cb * ca,  sb * sa);
            float2 m01 = make_float2(-sb * ca, -cb * sa);
            float2 m10 = make_float2(sb * ca,  -cb * sa);
            float2 m11 = make_float2(cb * ca,  -sb * sa);
            const float2 em = make_float2(cg, -sg);
            const float2 ep = make_float2(cg,  sg);
            m00 = cmul(em, m00); m01 = cmul(em, m01);
            m10 = cmul(ep, m10); m11 = cmul(ep, m11);
            ap1(s, 8 >> q, m00, m01, m10, m11);
        }
#pragma unroll
        for (int k = 0; k < 6; k++) {
            const float phi = qp[st + 12 + k] * 0.5f;
            float sp, cp;
            sincosf(phi, &sp, &cp);
            const float2 em = make_float2(cp, -sp);
            const float2 ep = make_float2(cp,  sp);
            const int bc = 8 >> pc_[k];
            const int bt = 8 >> pt_[k];
#pragma unroll
            for (int base = 0; base < 16; base++) {
                if (!(base & (bc | bt))) {
                    const int i01 = base | bt, i10 = base | bc, i11 = base | bc | bt;
                    float2 t00 = s[base], t01 = s[i01], t10 = s[i10], t11 = s[i11];
                    s[base] = cmul(em, t00);
                    s[i01]  = cmul(ep, t01);
                    s[i10]  = cmul(em, t11);
                    s[i11]  = cmul(ep, t10);
                }
            }
        }
    }

    float z[4];
#pragma unroll
    for (int w = 0; w < 4; w++) {
        const int bit = 8 >> w;
        float zv = 0.f;
#pragma unroll
        for (int i = 0; i < 16; i++) {
            const float p = s[i].x * s[i].x + s[i].y * s[i].y;
            zv += (i & bit) ? -p : p;
        }
        z[w] = zv;
    }

#pragma unroll
    for (int k = 0; k < 10; k++) {
        float o = pb[k];
#pragma unroll
        for (int j = 0; j < 4; j++) o = fmaf(z[j], pw[k * 4 + j], o);
        out[img * 10 + k] = o;
    }
}

// ---------------------------------------------------------------------------
extern "C" void kernel_launch(void* const* d_in, const int* in_sizes, int n_in,
                              void* d_out, int out_size)
{
    const float* x    = (const float*)d_in[0];
    const float* c1w  = (const float*)d_in[1];
    const float* c1b  = (const float*)d_in[2];
    const float* c2w  = (const float*)d_in[3];
    const float* c2b  = (const float*)d_in[4];
    const float* dw   = (const float*)d_in[5];
    const float* db   = (const float*)d_in[6];
    const float* qp   = (const float*)d_in[7];
    const float* pw   = (const float*)d_in[8];
    const float* pb   = (const float*)d_in[9];
    float* out = (float*)d_out;

    int B = in_sizes[0] / 784;
    if (B > B_MAX) B = B_MAX;

    cudaFuncSetAttribute(k2_mma,
                         cudaFuncAttributeMaxDynamicSharedMemorySize,
                         K2_SMEM_BYTES);

    k1_conv1<<<B, 196>>>(x, c1w, c1b);
    k2_mma<<<B, 256, K2_SMEM_BYTES>>>(c2w, c2b, dw, db);
    k3_quantum_post<<<(B + 127) / 128, 128>>>(qp, pw, pb, out, B);
}